// round 12
// baseline (speedup 1.0000x reference)
#include <cuda_runtime.h>
#include <cstdint>

// Heston Monte Carlo: 65536 paths x 512 steps.
// Inputs:  d_in[0] = Z_vol  [65536, 512, 2] f32 (only [:,:,0] used)
//          d_in[1] = Z_price[65536, 512]    f32
// Output:  d_out = S [65536,513] f32 followed by V [65536,513] f32
//
// Design: 64 paths/block (1 thread/path). cp.async 4-stage pipeline with
// depth-3 prefetch keeps DRAM loads continuously in flight; compute writes
// (S,V) in place over the zvol float2 tile; cooperative coalesced store.

#define NSTEPS   512
#define NP1      513
#define BATCH    65536
#define TPB      64
#define CHUNK    8
#define NCHUNKS  (NSTEPS / CHUNK)
#define NSTAGE   4
#define PITCH    (CHUNK + 1)   // 9: conflict-free for both tiles

__device__ __forceinline__ uint32_t smem_u32(const void* p) {
    return (uint32_t)__cvta_generic_to_shared(p);
}
__device__ __forceinline__ void cp_async8(uint32_t s, const void* g) {
    asm volatile("cp.async.ca.shared.global [%0], [%1], 8;\n" :: "r"(s), "l"(g));
}
__device__ __forceinline__ void cp_async4(uint32_t s, const void* g) {
    asm volatile("cp.async.ca.shared.global [%0], [%1], 4;\n" :: "r"(s), "l"(g));
}
__device__ __forceinline__ void cp_commit() {
    asm volatile("cp.async.commit_group;\n" ::: "memory");
}
template <int N>
__device__ __forceinline__ void cp_wait() {
    asm volatile("cp.async.wait_group %0;\n" :: "n"(N) : "memory");
}

__global__ __launch_bounds__(TPB, 8) void heston_kernel(
    const float2* __restrict__ zvol,    // [BATCH][NSTEPS] float2
    const float*  __restrict__ zprice,  // [BATCH][NSTEPS]
    float* __restrict__ S_out,          // [BATCH][NP1]
    float* __restrict__ V_out)          // [BATCH][NP1]
{
    __shared__ float2 sV[NSTAGE][TPB * PITCH];  // zvol in; (S,V) out, in place
    __shared__ float  sP[NSTAGE][TPB * PITCH];  // zprice

    const int tid = threadIdx.x;
    const long long pbase  = (long long)blockIdx.x * TPB;
    const long long mypath = pbase + tid;

    // model constants
    const float dt       = 1.0f / 512.0f;
    const float sqrt_dt  = 0.04419417382415922f;     // sqrt(1/512)
    const float rho      = -0.7f;
    const float rho_perp = 0.7141428428542850f;      // sqrt(1-rho^2)
    const float V0f      = 0.055225f;                 // 0.235^2
    const float kth_dt   = 0.04f * dt;                // KAPPA*THETA*dt
    const float two_sdt  = 2.0f * sqrt_dt;            // SIGMA_V * sqrt_dt

    // t = 0 column (tiny, negligible traffic)
    S_out[mypath * NP1] = 100.0f;
    V_out[mypath * NP1] = V0f;

    // ---- cp.async issue of one chunk into stage st (coalesced) ----
    auto issue_chunk = [&](int ck, int st) {
        const int t0 = ck * CHUNK;
        #pragma unroll
        for (int k = 0; k < CHUNK; k++) {
            const int i   = k * TPB + tid;
            const int row = i >> 3;          // path within block
            const int col = i & 7;           // step within chunk
            const long long g = (pbase + row) * (long long)NSTEPS + t0 + col;
            cp_async8(smem_u32(&sV[st][row * PITCH + col]), &zvol[g]);
            cp_async4(smem_u32(&sP[st][row * PITCH + col]), &zprice[g]);
        }
    };

    // ---- prologue: fill 3 stages ----
    issue_chunk(0, 0); cp_commit();
    issue_chunk(1, 1); cp_commit();
    issue_chunk(2, 2); cp_commit();

    float V    = V0f;
    float logS = 0.0f;

    for (int ck = 0; ck < NCHUNKS; ck++) {
        const int st = ck & 3;

        cp_wait<2>();          // chunk ck landed (this thread's copies)
        __syncthreads();       // ... and everyone else's

        // issue chunk ck+3 into stage (ck+3)&3 (freed last iteration)
        if (ck + 3 < NCHUNKS) issue_chunk(ck + 3, (ck + 3) & 3);
        cp_commit();           // always commit (empty at tail) -> uniform accounting

        // ---- compute: thread owns its path row; overwrite tile with (S,V) ----
        {
            float2* myV2 = &sV[st][tid * PITCH];
            float*  myP  = &sP[st][tid * PITCH];
            #pragma unroll
            for (int c = 0; c < CHUNK; c++) {
                const float zv = myV2[c].x;
                const float zp = myP[c];

                const float Vpos = fmaxf(V, 0.0f);
                const float sv   = sqrtf(Vpos);
                float Vnext = fmaf(two_sdt * zv, sv, fmaf(-dt, Vpos, V + kth_dt));
                Vnext = fmaxf(Vnext, 0.0f);

                const float dB = sqrt_dt * fmaf(rho, zv, rho_perp * zp);
                logS = fmaf(sv, dB, fmaf(-0.5f * dt, Vpos, logS));

                float2 out;
                out.x = 100.0f * __expf(logS);   // S
                out.y = Vnext;                   // V
                myV2[c] = out;                   // single STS.64
                V = Vnext;
            }
        }
        __syncthreads();       // compute writes visible to cooperative store

        // ---- cooperative coalesced store of chunk ck ----
        {
            const int t0 = ck * CHUNK;
            #pragma unroll
            for (int k = 0; k < CHUNK; k++) {
                const int i   = k * TPB + tid;
                const int row = i >> 3;
                const int col = i & 7;
                const float2 sv2 = sV[st][row * PITCH + col];
                const long long o = (pbase + row) * (long long)NP1 + (t0 + 1 + col);
                S_out[o] = sv2.x;
                V_out[o] = sv2.y;
            }
        }
        // next iteration's top barrier orders these LDS reads before stage reuse
    }
}

extern "C" void kernel_launch(void* const* d_in, const int* in_sizes, int n_in,
                              void* d_out, int out_size) {
    const float2* zvol   = (const float2*)d_in[0];
    const float*  zprice = (const float*) d_in[1];
    float* S  = (float*)d_out;
    float* Vv = S + (size_t)BATCH * NP1;

    heston_kernel<<<BATCH / TPB, TPB>>>(zvol, zprice, S, Vv);
}

// round 13
// speedup vs baseline: 1.2057x; 1.2057x over previous
#include <cuda_runtime.h>

// Heston Monte Carlo: 65536 paths x 512 steps.
// Inputs:  d_in[0] = Z_vol  [65536, 512, 2] f32 (only [:,:,0] used)
//          d_in[1] = Z_price[65536, 512]    f32
// Output:  d_out = S [65536,513] f32 followed by V [65536,513] f32
//
// Warp-specialized design: 64 paths/block.
//   warps 0-1 (64 thr): consumers — compute recurrence, 1 thread/path, store.
//   warp  2   (32 thr): producer  — loads noise chunks GMEM->regs->SMEM,
//                                   decoupled from compute via a named-barrier
//                                   ring (4 stages), so DRAM loads issue
//                                   continuously at consumer pace.

#define NSTEPS   512
#define NP1      513
#define BATCH    65536
#define NPATH    64                 // paths per block
#define TPB      96                 // 64 consumers + 32 producers
#define CHUNK    8
#define NCHUNKS  (NSTEPS / CHUNK)   // 64
#define NSTAGE   4
#define PITCH    (CHUNK + 1)        // 9 -> conflict-free/2-way smem layouts

// named barrier ids: FULL[s] = 1+s (s=0..3), EMPTY[s] = 5+s, MID = 9
#define BAR_SYNC(id, cnt)   asm volatile("bar.sync %0, %1;"   :: "r"(id), "r"(cnt) : "memory")
#define BAR_ARRIVE(id, cnt) asm volatile("bar.arrive %0, %1;" :: "r"(id), "r"(cnt) : "memory")

__global__ __launch_bounds__(TPB, 7) void heston_kernel(
    const float2* __restrict__ zvol,    // [BATCH][NSTEPS] float2 (use .x)
    const float*  __restrict__ zprice,  // [BATCH][NSTEPS]
    float* __restrict__ S_out,          // [BATCH][NP1]
    float* __restrict__ V_out)          // [BATCH][NP1]
{
    __shared__ float2 sV[NSTAGE][NPATH * PITCH];  // zvol in; (S,V) out in place
    __shared__ float  sP[NSTAGE][NPATH * PITCH];  // zprice

    const int tid = threadIdx.x;
    const int wid = tid >> 5;
    const long long pbase = (long long)blockIdx.x * NPATH;

    // model constants
    const float dt       = 1.0f / 512.0f;
    const float sqrt_dt  = 0.04419417382415922f;     // sqrt(1/512)
    const float rho      = -0.7f;
    const float rho_perp = 0.7141428428542850f;      // sqrt(1-rho^2)
    const float V0f      = 0.055225f;                 // 0.235^2
    const float kth_dt   = 0.04f * dt;                // KAPPA*THETA*dt
    const float two_sdt  = 2.0f * sqrt_dt;            // SIGMA_V * sqrt_dt

    if (wid < 2) {
        // ================= CONSUMERS (64 threads, 1 path each) =================
        const int ctid = tid;                       // 0..63
        const long long mypath = pbase + ctid;

        // t = 0 column (tiny)
        S_out[mypath * NP1] = 100.0f;
        V_out[mypath * NP1] = V0f;

        float V    = V0f;
        float logS = 0.0f;

        for (int ck = 0; ck < NCHUNKS; ck++) {
            const int s = ck & (NSTAGE - 1);

            BAR_SYNC(1 + s, TPB);                   // wait FULL[s]

            // compute 8 steps; overwrite zvol slot with (S,V)
            {
                float2* myV2 = &sV[s][ctid * PITCH];
                float*  myP  = &sP[s][ctid * PITCH];
                #pragma unroll
                for (int c = 0; c < CHUNK; c++) {
                    const float zv = myV2[c].x;
                    const float zp = myP[c];

                    const float Vpos = fmaxf(V, 0.0f);
                    const float sv   = sqrtf(Vpos);
                    float Vnext = fmaf(two_sdt * zv, sv, fmaf(-dt, Vpos, V + kth_dt));
                    Vnext = fmaf(0.0f, 0.0f, fmaxf(Vnext, 0.0f));

                    const float dB = sqrt_dt * fmaf(rho, zv, rho_perp * zp);
                    logS = fmaf(sv, dB, fmaf(-0.5f * dt, Vpos, logS));

                    float2 out;
                    out.x = 100.0f * __expf(logS);  // S
                    out.y = Vnext;                  // V
                    myV2[c] = out;
                    V = Vnext;
                }
            }

            BAR_SYNC(9, NPATH);                     // consumer-only barrier

            // cooperative coalesced store of chunk ck
            {
                const int t0 = ck * CHUNK;
                #pragma unroll
                for (int k = 0; k < CHUNK; k++) {
                    const int i   = k * NPATH + ctid;
                    const int row = i >> 3;
                    const int col = i & 7;
                    const float2 r = sV[s][row * PITCH + col];
                    const long long o = (pbase + row) * (long long)NP1 + (t0 + 1 + col);
                    S_out[o] = r.x;
                    V_out[o] = r.y;
                }
            }

            BAR_ARRIVE(5 + s, TPB);                 // release EMPTY[s]
        }
    } else {
        // ================= PRODUCER (32 threads) =================
        const int lane = tid & 31;
        const int rbase = lane >> 3;                // row offset within group of 4
        const int col   = lane & 7;

        float2 rzv[16];
        float  rzp[16];

        // prologue: load chunk 0 into registers
        #pragma unroll
        for (int g = 0; g < 16; g++) {
            const int row = g * 4 + rbase;
            const long long gidx = (pbase + row) * (long long)NSTEPS + col;
            rzv[g] = zvol[gidx];
            rzp[g] = zprice[gidx];
        }

        for (int ck = 0; ck < NCHUNKS; ck++) {
            const int s = ck & (NSTAGE - 1);

            if (ck >= NSTAGE) BAR_SYNC(5 + s, TPB); // ring backpressure

            // publish chunk ck (regs -> stage s)
            #pragma unroll
            for (int g = 0; g < 16; g++) {
                const int row = g * 4 + rbase;
                sV[s][row * PITCH + col] = rzv[g];
                sP[s][row * PITCH + col] = rzp[g];
            }
            __threadfence_block();
            BAR_ARRIVE(1 + s, TPB);                 // signal FULL[s]

            // issue next chunk's loads immediately (no wait until next STS)
            if (ck + 1 < NCHUNKS) {
                const int t0n = (ck + 1) * CHUNK;
                #pragma unroll
                for (int g = 0; g < 16; g++) {
                    const int row = g * 4 + rbase;
                    const long long gidx = (pbase + row) * (long long)NSTEPS + t0n + col;
                    rzv[g] = zvol[gidx];
                    rzp[g] = zprice[gidx];
                }
            }
        }
    }
}

extern "C" void kernel_launch(void* const* d_in, const int* in_sizes, int n_in,
                              void* d_out, int out_size) {
    const float2* zvol   = (const float2*)d_in[0];
    const float*  zprice = (const float*) d_in[1];
    float* S  = (float*)d_out;
    float* Vv = S + (size_t)BATCH * NP1;

    heston_kernel<<<BATCH / NPATH, TPB>>>(zvol, zprice, S, Vv);
}

// round 14
// speedup vs baseline: 1.2492x; 1.0361x over previous
#include <cuda_runtime.h>

// Heston Monte Carlo: 65536 paths x 512 steps.
// Inputs:  d_in[0] = Z_vol  [65536, 512, 2] f32 (only [:,:,0] used)
//          d_in[1] = Z_price[65536, 512]    f32
// Output:  d_out = S [65536,513] f32 followed by V [65536,513] f32
//
// Warp-autonomous design: each warp owns 32 paths end-to-end with a private
// smem transpose tile. NO block-level barriers — only __syncwarp — so warps
// free-run and stagger their DRAM bursts instead of convoying on
// __syncthreads. Register depth-1 prefetch hides load latency under compute.

#define NSTEPS   512
#define NP1      513
#define BATCH    65536
#define TPB      64                  // 2 independent warps per block
#define NWARP    (TPB / 32)
#define CHUNK    16
#define NCHUNKS  (NSTEPS / CHUNK)    // 32
#define PITCH    17                  // odd float stride -> conflict-free banks

__global__ __launch_bounds__(TPB, 8) void heston_kernel(
    const float2* __restrict__ zvol,    // [BATCH][NSTEPS] float2 (use .x)
    const float*  __restrict__ zprice,  // [BATCH][NSTEPS]
    float* __restrict__ S_out,          // [BATCH][NP1]
    float* __restrict__ V_out)          // [BATCH][NP1]
{
    __shared__ float sZV[NWARP][32 * PITCH];  // zv in -> S out (in place)
    __shared__ float sZP[NWARP][32 * PITCH];  // zp in -> V out (in place)

    const int tid  = threadIdx.x;
    const int w    = tid >> 5;
    const int lane = tid & 31;
    const long long pbase  = (long long)blockIdx.x * TPB + w * 32;  // warp's 32 paths
    const long long mypath = pbase + lane;

    float* ZV = sZV[w];
    float* ZP = sZP[w];

    // model constants
    const float dt       = 1.0f / 512.0f;
    const float sqrt_dt  = 0.04419417382415922f;     // sqrt(1/512)
    const float rho      = -0.7f;
    const float rho_perp = 0.7141428428542850f;      // sqrt(1-rho^2)
    const float V0f      = 0.055225f;                 // 0.235^2
    const float kth_dt   = 0.04f * dt;                // KAPPA*THETA*dt (KAPPA=1)
    const float two_sdt  = 2.0f * sqrt_dt;            // SIGMA_V * sqrt_dt

    // t = 0 column (tiny, negligible traffic)
    S_out[mypath * NP1] = 100.0f;
    V_out[mypath * NP1] = V0f;

    float pzv[CHUNK];   // prefetched zv (next chunk)
    float pzp[CHUNK];   // prefetched zp

    // ---- prologue: load + stage chunk 0 (coalesced: half-warp per path row) ----
    #pragma unroll
    for (int k = 0; k < CHUNK; k++) {
        const int i   = k * 32 + lane;
        const int row = i >> 4;          // path within warp (0..31)
        const int col = i & 15;          // step within chunk
        const long long g = (pbase + row) * (long long)NSTEPS + col;
        pzv[k] = zvol[g].x;
        pzp[k] = zprice[g];
    }
    #pragma unroll
    for (int k = 0; k < CHUNK; k++) {
        const int i   = k * 32 + lane;
        const int row = i >> 4;
        const int col = i & 15;
        ZV[row * PITCH + col] = pzv[k];
        ZP[row * PITCH + col] = pzp[k];
    }
    __syncwarp();

    float V    = V0f;
    float logS = 0.0f;

    for (int ck = 0; ck < NCHUNKS; ck++) {
        const bool has_next = (ck + 1 < NCHUNKS);

        // ---- prefetch chunk ck+1 into registers (hidden under compute) ----
        if (has_next) {
            const int t0n = (ck + 1) * CHUNK;
            #pragma unroll
            for (int k = 0; k < CHUNK; k++) {
                const int i   = k * 32 + lane;
                const int row = i >> 4;
                const int col = i & 15;
                const long long g = (pbase + row) * (long long)NSTEPS + t0n + col;
                pzv[k] = zvol[g].x;
                pzp[k] = zprice[g];
            }
        }

        // ---- compute: lane owns path row 'lane'; overwrite tile with S/V ----
        {
            float* myZV = &ZV[lane * PITCH];
            float* myZP = &ZP[lane * PITCH];
            #pragma unroll
            for (int c = 0; c < CHUNK; c++) {
                const float zv = myZV[c];
                const float zp = myZP[c];

                const float Vpos = fmaxf(V, 0.0f);
                const float sv   = sqrtf(Vpos);
                float Vnext = fmaf(two_sdt * zv, sv, fmaf(-dt, Vpos, V + kth_dt));
                Vnext = fmaxf(Vnext, 0.0f);

                const float dB = sqrt_dt * fmaf(rho, zv, rho_perp * zp);
                logS = fmaf(sv, dB, fmaf(-0.5f * dt, Vpos, logS));

                myZV[c] = 100.0f * __expf(logS);   // S
                myZP[c] = Vnext;                   // V
                V = Vnext;
            }
        }
        __syncwarp();   // compute writes visible to cooperative store

        // ---- cooperative coalesced store of chunk ck (warp-local) ----
        {
            const int t0 = ck * CHUNK;
            #pragma unroll
            for (int k = 0; k < CHUNK; k++) {
                const int i   = k * 32 + lane;
                const int row = i >> 4;
                const int col = i & 15;
                const long long o = (pbase + row) * (long long)NP1 + (t0 + 1 + col);
                S_out[o] = ZV[row * PITCH + col];
                V_out[o] = ZP[row * PITCH + col];
            }
        }
        __syncwarp();   // store reads done before tile reuse

        // ---- stage prefetched chunk into the tile ----
        if (has_next) {
            #pragma unroll
            for (int k = 0; k < CHUNK; k++) {
                const int i   = k * 32 + lane;
                const int row = i >> 4;
                const int col = i & 15;
                ZV[row * PITCH + col] = pzv[k];
                ZP[row * PITCH + col] = pzp[k];
            }
        }
        __syncwarp();   // staged data visible before next compute
    }
}

extern "C" void kernel_launch(void* const* d_in, const int* in_sizes, int n_in,
                              void* d_out, int out_size) {
    const float2* zvol   = (const float2*)d_in[0];
    const float*  zprice = (const float*) d_in[1];
    float* S  = (float*)d_out;
    float* Vv = S + (size_t)BATCH * NP1;

    heston_kernel<<<BATCH / TPB, TPB>>>(zvol, zprice, S, Vv);
}

// round 15
// speedup vs baseline: 1.5731x; 1.2593x over previous
#include <cuda_runtime.h>

// Heston Monte Carlo: 65536 paths x 512 steps.
// Inputs:  d_in[0] = Z_vol  [65536, 512, 2] f32 (only [:,:,0] used)
//          d_in[1] = Z_price[65536, 512]    f32
// Output:  d_out = S [65536,513] f32 followed by V [65536,513] f32
//
// Depth-2 pipelined version of the best (209us) kernel:
//   iteration ck: issue LDGs for chunk ck+2 (into regset freed last iter),
//   stage regset holding chunk ck+1 (issued a FULL iteration ago -> landed),
//   compute ck in smem (in-place S/V overwrite), BAR, coalesced store, BAR.
// Every warp keeps ~2 load bursts in flight at all times.

#define NSTEPS   512
#define NP1      513
#define BATCH    65536
#define TPB      64
#define CHUNK    16
#define NCHUNKS  (NSTEPS / CHUNK)    // 32
#define PITCH    17                  // scalar pitch: conflict-free compute reads

__global__ __launch_bounds__(TPB, 8) void heston_kernel(
    const float* __restrict__ zvolx,    // [BATCH][NSTEPS][2] f32, we read [..][0]
    const float* __restrict__ zprice,   // [BATCH][NSTEPS]
    float* __restrict__ S_out,          // [BATCH][NP1]
    float* __restrict__ V_out)          // [BATCH][NP1]
{
    __shared__ float sZV[2][TPB * PITCH];  // zv in -> S out (in place)
    __shared__ float sZP[2][TPB * PITCH];  // zp in -> V out (in place)

    const int tid = threadIdx.x;
    const long long pbase  = (long long)blockIdx.x * TPB;
    const long long mypath = pbase + tid;

    // fixed per-thread cooperative coords: i = k*TPB + tid
    const int crow = tid >> 4;          // row base (k adds 4 per step)
    const int ccol = tid & 15;          // step-within-chunk (constant!)

    // model constants
    const float dt       = 1.0f / 512.0f;
    const float sqrt_dt  = 0.04419417382415922f;     // sqrt(1/512)
    const float rho      = -0.7f;
    const float rho_perp = 0.7141428428542850f;      // sqrt(1-rho^2)
    const float V0f      = 0.055225f;                 // 0.235^2
    const float kth_dt   = 0.04f * dt;                // KAPPA*THETA*dt (KAPPA=1)
    const float two_sdt  = 2.0f * sqrt_dt;            // SIGMA_V * sqrt_dt

    // t = 0 column (tiny, negligible)
    S_out[mypath * NP1] = 100.0f;
    V_out[mypath * NP1] = V0f;

    float azv[CHUNK], azp[CHUNK];   // regset A
    float bzv[CHUNK], bzp[CHUNK];   // regset B

    // per-thread global base for cooperative loads (element index of [row=crow, col=ccol])
    const long long gbase = (pbase + crow) * (long long)NSTEPS + ccol;

    #define LOAD_SET(zvr, zpr, t0)                                          \
        _Pragma("unroll")                                                    \
        for (int k = 0; k < CHUNK; k++) {                                    \
            const long long g = gbase + (long long)(k * 4) * NSTEPS + (t0);  \
            zvr[k] = zvolx[2 * g];                                           \
            zpr[k] = zprice[g];                                              \
        }

    #define STAGE_SET(zvr, zpr, buf)                                        \
        _Pragma("unroll")                                                    \
        for (int k = 0; k < CHUNK; k++) {                                    \
            const int sidx = (k * 4 + crow) * PITCH + ccol;                  \
            sZV[buf][sidx] = zvr[k];                                         \
            sZP[buf][sidx] = zpr[k];                                         \
        }

    // ---- prologue: A<-chunk0, B<-chunk1, stage A into buf0 ----
    LOAD_SET(azv, azp, 0)
    LOAD_SET(bzv, bzp, CHUNK)
    STAGE_SET(azv, azp, 0)
    __syncthreads();

    float V    = V0f;
    float logS = 0.0f;

    #define COMPUTE_CHUNK(buf)                                               \
        {                                                                    \
            float* myZV = &sZV[buf][tid * PITCH];                            \
            float* myZP = &sZP[buf][tid * PITCH];                            \
            _Pragma("unroll")                                                \
            for (int c = 0; c < CHUNK; c++) {                                \
                const float zv = myZV[c];                                    \
                const float zp = myZP[c];                                    \
                const float Vpos = fmaxf(V, 0.0f);                           \
                const float sv   = sqrtf(Vpos);                              \
                float Vnext = fmaf(two_sdt * zv, sv,                         \
                                   fmaf(-dt, Vpos, V + kth_dt));             \
                Vnext = fmaxf(Vnext, 0.0f);                                  \
                const float dB = sqrt_dt * fmaf(rho, zv, rho_perp * zp);     \
                logS = fmaf(sv, dB, fmaf(-0.5f * dt, Vpos, logS));           \
                myZV[c] = 100.0f * __expf(logS);  /* S */                    \
                myZP[c] = Vnext;                  /* V */                    \
                V = Vnext;                                                   \
            }                                                                \
        }

    #define STORE_CHUNK(buf, t0)                                             \
        {                                                                     \
            _Pragma("unroll")                                                 \
            for (int k = 0; k < CHUNK; k++) {                                 \
                const int sidx = (k * 4 + crow) * PITCH + ccol;               \
                const long long o = (pbase + k * 4 + crow) * (long long)NP1   \
                                    + ((t0) + 1 + ccol);                      \
                S_out[o] = sZV[buf][sidx];                                    \
                V_out[o] = sZP[buf][sidx];                                    \
            }                                                                 \
        }

    #pragma unroll 1
    for (int cp = 0; cp < NCHUNKS / 2; cp++) {
        const int ck0 = 2 * cp;            // even chunk -> buf0, stages B->buf1, loads->A
        const int ck1 = 2 * cp + 1;        // odd  chunk -> buf1, stages A->buf0, loads->B

        // ---- even iteration ----
        if (ck0 + 2 < NCHUNKS) { LOAD_SET(azv, azp, (ck0 + 2) * CHUNK) }  // A <- ck0+2
        STAGE_SET(bzv, bzp, 1)                                            // B (ck0+1) -> buf1
        COMPUTE_CHUNK(0)
        __syncthreads();
        STORE_CHUNK(0, ck0 * CHUNK)
        __syncthreads();

        // ---- odd iteration ----
        if (ck1 + 2 < NCHUNKS) { LOAD_SET(bzv, bzp, (ck1 + 2) * CHUNK) }  // B <- ck1+2
        if (ck0 + 2 < NCHUNKS) { STAGE_SET(azv, azp, 0) }                 // A (ck0+2) -> buf0
        COMPUTE_CHUNK(1)
        __syncthreads();
        STORE_CHUNK(1, ck1 * CHUNK)
        __syncthreads();
    }

    #undef LOAD_SET
    #undef STAGE_SET
    #undef COMPUTE_CHUNK
    #undef STORE_CHUNK
}

extern "C" void kernel_launch(void* const* d_in, const int* in_sizes, int n_in,
                              void* d_out, int out_size) {
    const float* zvolx  = (const float*)d_in[0];
    const float* zprice = (const float*)d_in[1];
    float* S  = (float*)d_out;
    float* Vv = S + (size_t)BATCH * NP1;

    heston_kernel<<<BATCH / TPB, TPB>>>(zvolx, zprice, S, Vv);
}